// round 1
// baseline (speedup 1.0000x reference)
#include <cuda_runtime.h>
#include <math.h>

// Problem constants
#define B_ 4
#define S_ 2048
#define D_ 1024
#define H_ 16
#define DH_ 64
#define DFF_ 4096

// Scratch layout (floats)
#define SZ_HEADS (4LL*16*2048*64)      // 8388608
#define OFF_Q    0LL
#define OFF_K    8388608LL
#define OFF_V    16777216LL
#define OFF_ATT  25165824LL
#define OFF_PROJ 33554432LL
#define OFF_LN1  41943040LL
#define OFF_FFH  50331648LL            // 33554432 floats
#define OFF_MLP  83886080LL
#define SCRATCH_TOTAL 92274688LL

__device__ float g_scratch[SCRATCH_TOTAL];

// ---------------------------------------------------------------------------
// QKV GEMM: C[m, h*192+e] = sum_k X[m,k] * Wqkv[h,k,e], scattered to Q/K/V
// [B,H,S,DH] buffers. Tile 128(M) x 64(N) x 8(K), 256 threads, 8x4 per thread.
// ---------------------------------------------------------------------------
__global__ void qkv_gemm_kernel(const float* __restrict__ X,
                                const float* __restrict__ Wqkv,
                                float* __restrict__ Qo,
                                float* __restrict__ Ko,
                                float* __restrict__ Vo)
{
    __shared__ float As[8][128];
    __shared__ float Bs[8][64];

    const int tid = threadIdx.x;
    const int m0 = blockIdx.y * 128;
    const int n0 = blockIdx.x * 64;
    const int head = n0 / 192;
    const int e0 = n0 % 192;              // 0, 64 or 128
    const int ty = tid >> 4, tx = tid & 15;

    const float* Bp = Wqkv + (long long)head * D_ * 192 + e0;

    float acc[8][4];
#pragma unroll
    for (int i = 0; i < 8; i++)
#pragma unroll
        for (int j = 0; j < 4; j++) acc[i][j] = 0.0f;

    const int ar_ = tid >> 1, ac_ = (tid & 1) * 4;
    const int br_ = tid >> 4, bc_ = (tid & 15) * 4;

    for (int k0 = 0; k0 < D_; k0 += 8) {
        float4 av = *(const float4*)&X[(long long)(m0 + ar_) * D_ + k0 + ac_];
        As[ac_ + 0][ar_] = av.x;
        As[ac_ + 1][ar_] = av.y;
        As[ac_ + 2][ar_] = av.z;
        As[ac_ + 3][ar_] = av.w;
        if (tid < 128) {
            *(float4*)&Bs[br_][bc_] =
                *(const float4*)&Bp[(long long)(k0 + br_) * 192 + bc_];
        }
        __syncthreads();
#pragma unroll
        for (int k = 0; k < 8; k++) {
            float ar[8], br[4];
            *(float4*)&ar[0] = *(float4*)&As[k][ty * 4];
            *(float4*)&ar[4] = *(float4*)&As[k][64 + ty * 4];
            *(float4*)&br[0] = *(float4*)&Bs[k][tx * 4];
#pragma unroll
            for (int i = 0; i < 8; i++)
#pragma unroll
                for (int j = 0; j < 4; j++)
                    acc[i][j] += ar[i] * br[j];
        }
        __syncthreads();
    }

    float* dst = (e0 == 0) ? Qo : (e0 == 64) ? Ko : Vo;
#pragma unroll
    for (int i = 0; i < 8; i++) {
        int m = m0 + ((i < 4) ? (ty * 4 + i) : (64 + ty * 4 + (i - 4)));
        int bb = m >> 11;          // / S_
        int ss = m & 2047;         // % S_
        float4 v = make_float4(acc[i][0], acc[i][1], acc[i][2], acc[i][3]);
        *(float4*)&dst[(((long long)bb * H_ + head) * S_ + ss) * DH_ + tx * 4] = v;
    }
}

// ---------------------------------------------------------------------------
// Generic SGEMM + bias (+ optional exact GELU). 128x128x8 tiles, 256 threads,
// 8x8 per thread (2x2 blocks of 4x4). A row-major [M,K], B row-major [K,N].
// ---------------------------------------------------------------------------
__device__ __forceinline__ float gelu_exact(float x) {
    return 0.5f * x * (1.0f + erff(x * 0.70710678118654752f));
}

__global__ void sgemm_bias_kernel(const float* __restrict__ A,
                                  const float* __restrict__ Bm,
                                  const float* __restrict__ bias,
                                  float* __restrict__ C,
                                  int N, int K, int do_gelu)
{
    __shared__ float As[8][128];
    __shared__ float Bs[8][128];

    const int tid = threadIdx.x;
    const int m0 = blockIdx.y * 128;
    const int n0 = blockIdx.x * 128;
    const int ty = tid >> 4, tx = tid & 15;

    float acc[8][8];
#pragma unroll
    for (int i = 0; i < 8; i++)
#pragma unroll
        for (int j = 0; j < 8; j++) acc[i][j] = 0.0f;

    const int ar_ = tid >> 1, ac_ = (tid & 1) * 4;
    const int br_ = tid >> 5, bc_ = (tid & 31) * 4;

    for (int k0 = 0; k0 < K; k0 += 8) {
        float4 av = *(const float4*)&A[(long long)(m0 + ar_) * K + k0 + ac_];
        As[ac_ + 0][ar_] = av.x;
        As[ac_ + 1][ar_] = av.y;
        As[ac_ + 2][ar_] = av.z;
        As[ac_ + 3][ar_] = av.w;
        *(float4*)&Bs[br_][bc_] =
            *(const float4*)&Bm[(long long)(k0 + br_) * N + n0 + bc_];
        __syncthreads();
#pragma unroll
        for (int k = 0; k < 8; k++) {
            float ar[8], br[8];
            *(float4*)&ar[0] = *(float4*)&As[k][ty * 4];
            *(float4*)&ar[4] = *(float4*)&As[k][64 + ty * 4];
            *(float4*)&br[0] = *(float4*)&Bs[k][tx * 4];
            *(float4*)&br[4] = *(float4*)&Bs[k][64 + tx * 4];
#pragma unroll
            for (int i = 0; i < 8; i++)
#pragma unroll
                for (int j = 0; j < 8; j++)
                    acc[i][j] += ar[i] * br[j];
        }
        __syncthreads();
    }

#pragma unroll
    for (int jb = 0; jb < 2; jb++) {
        int c = n0 + jb * 64 + tx * 4;
        float4 bv = *(const float4*)&bias[c];
#pragma unroll
        for (int ib = 0; ib < 2; ib++) {
#pragma unroll
            for (int i = 0; i < 4; i++) {
                int r = m0 + ib * 64 + ty * 4 + i;
                float4 v;
                v.x = acc[ib * 4 + i][jb * 4 + 0] + bv.x;
                v.y = acc[ib * 4 + i][jb * 4 + 1] + bv.y;
                v.z = acc[ib * 4 + i][jb * 4 + 2] + bv.z;
                v.w = acc[ib * 4 + i][jb * 4 + 3] + bv.w;
                if (do_gelu) {
                    v.x = gelu_exact(v.x);
                    v.y = gelu_exact(v.y);
                    v.z = gelu_exact(v.z);
                    v.w = gelu_exact(v.w);
                }
                *(float4*)&C[(long long)r * N + c] = v;
            }
        }
    }
}

// ---------------------------------------------------------------------------
// Causal flash attention, fp32. One block = 64 query rows for one (b,h).
// 256 threads as 16x16 grid; each thread computes a 4x4 score block and owns
// a 4(row) x 4(d) output slice. P is exchanged via smem (overlaying K tile).
// ---------------------------------------------------------------------------
__global__ void flash_attn_kernel(const float* __restrict__ Q,
                                  const float* __restrict__ K,
                                  const float* __restrict__ V,
                                  float* __restrict__ O)
{
    extern __shared__ float sm[];
    float* Qs = sm;                 // 64 x 68
    float* Ks = sm + 64 * 68;       // 64 x 68  (reused as Ps)
    float* Vs = sm + 2 * 64 * 68;   // 64 x 68
    float* Ps = Ks;

    const int tid = threadIdx.x;
    const int it = blockIdx.x;
    const int bh = blockIdx.y;
    const int i0 = it * 64;
    const int tr = tid >> 4, tc = tid & 15;
    const int r0 = tr * 4, c0 = tc * 4;

    const float* Qg = Q + (long long)bh * S_ * DH_;
    const float* Kg = K + (long long)bh * S_ * DH_;
    const float* Vg = V + (long long)bh * S_ * DH_;

    // load Q tile
#pragma unroll
    for (int i = 0; i < 4; i++) {
        int f4 = tid + i * 256;
        int row = f4 >> 4, col = (f4 & 15) * 4;
        *(float4*)&Qs[row * 68 + col] = *(const float4*)&Qg[(i0 + row) * DH_ + col];
    }

    float o[4][4];
    float m[4], l[4];
#pragma unroll
    for (int i = 0; i < 4; i++) {
        m[i] = -1e30f; l[i] = 0.0f;
#pragma unroll
        for (int j = 0; j < 4; j++) o[i][j] = 0.0f;
    }

    for (int jt = 0; jt <= it; jt++) {
        const int j0 = jt * 64;
        // K/V tiles (previous iter finished with smem at loop-end sync)
#pragma unroll
        for (int i = 0; i < 4; i++) {
            int f4 = tid + i * 256;
            int row = f4 >> 4, col = (f4 & 15) * 4;
            *(float4*)&Ks[row * 68 + col] = *(const float4*)&Kg[(j0 + row) * DH_ + col];
            *(float4*)&Vs[row * 68 + col] = *(const float4*)&Vg[(j0 + row) * DH_ + col];
        }
        __syncthreads();

        // scores 4x4
        float s[4][4];
#pragma unroll
        for (int i = 0; i < 4; i++)
#pragma unroll
            for (int j = 0; j < 4; j++) s[i][j] = 0.0f;

        for (int d = 0; d < 64; d += 4) {
            float4 qv[4], kv[4];
#pragma unroll
            for (int i = 0; i < 4; i++) qv[i] = *(float4*)&Qs[(r0 + i) * 68 + d];
#pragma unroll
            for (int j = 0; j < 4; j++) kv[j] = *(float4*)&Ks[(c0 + j) * 68 + d];
#pragma unroll
            for (int i = 0; i < 4; i++)
#pragma unroll
                for (int j = 0; j < 4; j++)
                    s[i][j] += qv[i].x * kv[j].x + qv[i].y * kv[j].y +
                               qv[i].z * kv[j].z + qv[i].w * kv[j].w;
        }

        // scale + causal mask
#pragma unroll
        for (int i = 0; i < 4; i++)
#pragma unroll
            for (int j = 0; j < 4; j++) {
                float v = s[i][j] * 0.125f;
                if (j0 + c0 + j > i0 + r0 + i) v = -1e30f;
                s[i][j] = v;
            }

        // online softmax
        float p[4][4];
#pragma unroll
        for (int i = 0; i < 4; i++) {
            float rm = fmaxf(fmaxf(s[i][0], s[i][1]), fmaxf(s[i][2], s[i][3]));
#pragma unroll
            for (int off = 1; off <= 8; off <<= 1)
                rm = fmaxf(rm, __shfl_xor_sync(0xffffffffu, rm, off));
            float mn = fmaxf(m[i], rm);
            float corr = __expf(m[i] - mn);
            float rs = 0.0f;
#pragma unroll
            for (int j = 0; j < 4; j++) {
                p[i][j] = __expf(s[i][j] - mn);
                rs += p[i][j];
            }
#pragma unroll
            for (int off = 1; off <= 8; off <<= 1)
                rs += __shfl_xor_sync(0xffffffffu, rs, off);
            l[i] = l[i] * corr + rs;
            m[i] = mn;
#pragma unroll
            for (int j = 0; j < 4; j++) o[i][j] *= corr;
        }

        __syncthreads();   // everyone done reading Ks
#pragma unroll
        for (int i = 0; i < 4; i++)
#pragma unroll
            for (int j = 0; j < 4; j++)
                Ps[(r0 + i) * 68 + c0 + j] = p[i][j];
        __syncthreads();

        // O accumulation: o[i][d] += sum_c P[r0+i][c] * V[c][tc*4+d]
        for (int c4 = 0; c4 < 64; c4 += 4) {
            float4 pv[4], vv[4];
#pragma unroll
            for (int i = 0; i < 4; i++) pv[i] = *(float4*)&Ps[(r0 + i) * 68 + c4];
#pragma unroll
            for (int j = 0; j < 4; j++) vv[j] = *(float4*)&Vs[(c4 + j) * 68 + tc * 4];
#pragma unroll
            for (int i = 0; i < 4; i++) {
                o[i][0] += pv[i].x * vv[0].x + pv[i].y * vv[1].x + pv[i].z * vv[2].x + pv[i].w * vv[3].x;
                o[i][1] += pv[i].x * vv[0].y + pv[i].y * vv[1].y + pv[i].z * vv[2].y + pv[i].w * vv[3].y;
                o[i][2] += pv[i].x * vv[0].z + pv[i].y * vv[1].z + pv[i].z * vv[2].z + pv[i].w * vv[3].z;
                o[i][3] += pv[i].x * vv[0].w + pv[i].y * vv[1].w + pv[i].z * vv[2].w + pv[i].w * vv[3].w;
            }
        }
        __syncthreads();
    }

    // write heads concatenated: att[(b*S+s)*D + h*64 + d]
    const int b = bh >> 4, h = bh & 15;
#pragma unroll
    for (int i = 0; i < 4; i++) {
        float inv = 1.0f / l[i];
        float4 v = make_float4(o[i][0] * inv, o[i][1] * inv, o[i][2] * inv, o[i][3] * inv);
        *(float4*)&O[((long long)(b * S_ + i0 + r0 + i)) * D_ + h * 64 + tc * 4] = v;
    }
}

// ---------------------------------------------------------------------------
// Fused residual + LayerNorm over rows of 1024. One block (256 thr) per row.
// ---------------------------------------------------------------------------
__global__ void ln_kernel(const float* __restrict__ A,
                          const float* __restrict__ R,
                          const float* __restrict__ G,
                          const float* __restrict__ Be,
                          float* __restrict__ Out)
{
    const int row = blockIdx.x;
    const int tid = threadIdx.x;
    const long long base = (long long)row * D_;

    float4 va = *(const float4*)&A[base + tid * 4];
    float4 vb = *(const float4*)&R[base + tid * 4];
    float4 v = make_float4(va.x + vb.x, va.y + vb.y, va.z + vb.z, va.w + vb.w);

    float s = v.x + v.y + v.z + v.w;
    float ss = v.x * v.x + v.y * v.y + v.z * v.z + v.w * v.w;

    __shared__ float rs_[8], rss_[8];
#pragma unroll
    for (int off = 16; off >= 1; off >>= 1) {
        s += __shfl_xor_sync(0xffffffffu, s, off);
        ss += __shfl_xor_sync(0xffffffffu, ss, off);
    }
    int warp = tid >> 5, lane = tid & 31;
    if (lane == 0) { rs_[warp] = s; rss_[warp] = ss; }
    __syncthreads();
    if (warp == 0) {
        s = (lane < 8) ? rs_[lane] : 0.0f;
        ss = (lane < 8) ? rss_[lane] : 0.0f;
#pragma unroll
        for (int off = 4; off >= 1; off >>= 1) {
            s += __shfl_xor_sync(0xffffffffu, s, off);
            ss += __shfl_xor_sync(0xffffffffu, ss, off);
        }
        if (lane == 0) { rs_[0] = s; rss_[0] = ss; }
    }
    __syncthreads();
    s = rs_[0]; ss = rss_[0];

    const float mu = s * (1.0f / 1024.0f);
    const float var = ss * (1.0f / 1024.0f) - mu * mu;
    const float rstd = rsqrtf(var + 1e-5f);

    float4 g4 = *(const float4*)&G[tid * 4];
    float4 b4 = *(const float4*)&Be[tid * 4];
    float4 ov;
    ov.x = (v.x - mu) * rstd * g4.x + b4.x;
    ov.y = (v.y - mu) * rstd * g4.y + b4.y;
    ov.z = (v.z - mu) * rstd * g4.z + b4.z;
    ov.w = (v.w - mu) * rstd * g4.w + b4.w;
    *(float4*)&Out[base + tid * 4] = ov;
}

// ---------------------------------------------------------------------------
extern "C" void kernel_launch(void* const* d_in, const int* in_sizes, int n_in,
                              void* d_out, int out_size)
{
    (void)in_sizes; (void)n_in; (void)out_size;
    const float* x     = (const float*)d_in[0];
    const float* Wqkv  = (const float*)d_in[1];
    const float* Wproj = (const float*)d_in[2];
    const float* bproj = (const float*)d_in[3];
    const float* ln1g  = (const float*)d_in[4];
    const float* ln1b  = (const float*)d_in[5];
    const float* ln2g  = (const float*)d_in[6];
    const float* ln2b  = (const float*)d_in[7];
    const float* W1    = (const float*)d_in[8];
    const float* b1    = (const float*)d_in[9];
    const float* W2    = (const float*)d_in[10];
    const float* b2    = (const float*)d_in[11];
    float* out = (float*)d_out;

    float* scratch = nullptr;
    cudaGetSymbolAddress((void**)&scratch, g_scratch);

    float* Qb   = scratch + OFF_Q;
    float* Kb   = scratch + OFF_K;
    float* Vb   = scratch + OFF_V;
    float* ATT  = scratch + OFF_ATT;
    float* PROJ = scratch + OFF_PROJ;
    float* LN1  = scratch + OFF_LN1;
    float* FFH  = scratch + OFF_FFH;
    float* MLP  = scratch + OFF_MLP;

    // 1) QKV projection
    qkv_gemm_kernel<<<dim3(48, 64), 256>>>(x, Wqkv, Qb, Kb, Vb);

    // 2) causal flash attention
    const int smem = 3 * 64 * 68 * (int)sizeof(float);   // 52224 B
    cudaFuncSetAttribute(flash_attn_kernel,
                         cudaFuncAttributeMaxDynamicSharedMemorySize, smem);
    flash_attn_kernel<<<dim3(32, 64), 256, smem>>>(Qb, Kb, Vb, ATT);

    // 3) output projection + bias
    sgemm_bias_kernel<<<dim3(8, 64), 256>>>(ATT, Wproj, bproj, PROJ, 1024, 1024, 0);

    // 4) residual + LN1
    ln_kernel<<<8192, 256>>>(x, PROJ, ln1g, ln1b, LN1);

    // 5) MLP up + bias + exact GELU
    sgemm_bias_kernel<<<dim3(32, 64), 256>>>(LN1, W1, b1, FFH, 4096, 1024, 1);

    // 6) MLP down + bias
    sgemm_bias_kernel<<<dim3(8, 64), 256>>>(FFH, W2, b2, MLP, 1024, 4096, 0);

    // 7) residual + LN2 -> output
    ln_kernel<<<8192, 256>>>(LN1, MLP, ln2g, ln2b, out);
}

// round 2
// speedup vs baseline: 1.9222x; 1.9222x over previous
#include <cuda_runtime.h>
#include <math.h>

// Problem constants
#define B_ 4
#define S_ 2048
#define D_ 1024
#define H_ 16
#define DH_ 64
#define DFF_ 4096

// Scratch layout (floats)
#define OFF_Q    0LL
#define OFF_K    8388608LL
#define OFF_V    16777216LL
#define OFF_ATT  25165824LL
#define OFF_PROJ 33554432LL
#define OFF_LN1  41943040LL
#define OFF_FFH  50331648LL
#define OFF_MLP  83886080LL
#define SCRATCH_TOTAL 92274688LL

__device__ float g_scratch[SCRATCH_TOTAL];

// ---------------------------------------------------------------------------
// tf32 mma.sync helpers
// ---------------------------------------------------------------------------
__device__ __forceinline__ float to_tf32(float x) {
    float y;
    asm("cvt.rna.tf32.f32 %0, %1;" : "=f"(y) : "f"(x));
    return y;
}

__device__ __forceinline__ void mma_tf32(float c[4], const float a[4], const float b[2]) {
    asm volatile(
        "mma.sync.aligned.m16n8k8.row.col.f32.tf32.tf32.f32 "
        "{%0,%1,%2,%3}, {%4,%5,%6,%7}, {%8,%9}, {%0,%1,%2,%3};"
        : "+f"(c[0]), "+f"(c[1]), "+f"(c[2]), "+f"(c[3])
        : "r"(__float_as_uint(a[0])), "r"(__float_as_uint(a[1])),
          "r"(__float_as_uint(a[2])), "r"(__float_as_uint(a[3])),
          "r"(__float_as_uint(b[0])), "r"(__float_as_uint(b[1])));
}

__device__ __forceinline__ float gelu_exact(float x) {
    return 0.5f * x * (1.0f + erff(x * 0.70710678118654752f));
}

// ---------------------------------------------------------------------------
// Generic tf32 tensor-core GEMM: C[M,N] = A[M,K] @ B[K,N] + bias (+ GELU)
// BM=128 BN=128 BK=16, 256 threads (8 warps, 2x4), warp tile 64x32.
// ---------------------------------------------------------------------------
#define BM 128
#define BN 128
#define BK 16
#define ASTR 20     // As[m][k] stride (conflict-free fragment loads)
#define BSTR 136    // Bs[k][n] stride (conflict-free fragment loads)

__global__ void __launch_bounds__(256)
tf32_gemm_kernel(const float* __restrict__ A,
                 const float* __restrict__ Bm,
                 const float* __restrict__ bias,
                 float* __restrict__ C,
                 int N, int K, int do_gelu)
{
    __shared__ float As[BM * ASTR];
    __shared__ float Bs[BK * BSTR];

    const int tid  = threadIdx.x;
    const int warp = tid >> 5, lane = tid & 31;
    const int wm = warp >> 2, wn = warp & 3;
    const int g = lane >> 2, tg = lane & 3;
    const int m0 = blockIdx.y * BM, n0 = blockIdx.x * BN;

    // global staging indices
    const int ar = tid >> 2;          // A row within tile (0..63, +64)
    const int ak = (tid & 3) * 4;     // A k offset
    const int br = tid >> 5;          // B row (k) within tile (0..7, +8)
    const int bn = (lane) * 4;        // B col offset

    const float* Ap = A + (long long)m0 * K;
    const float* Bp = Bm + n0;

    float acc[4][4][4];
#pragma unroll
    for (int i = 0; i < 4; i++)
#pragma unroll
        for (int j = 0; j < 4; j++)
#pragma unroll
            for (int r = 0; r < 4; r++) acc[i][j][r] = 0.0f;

    float4 ra0, ra1, rb0, rb1;

    // prologue: load tile 0
    ra0 = *(const float4*)&Ap[(long long)ar * K + ak];
    ra1 = *(const float4*)&Ap[(long long)(ar + 64) * K + ak];
    rb0 = *(const float4*)&Bp[(long long)br * N + bn];
    rb1 = *(const float4*)&Bp[(long long)(br + 8) * N + bn];

#define STORE_STAGE()                                                          \
    {                                                                          \
        float4 t;                                                              \
        t = ra0;                                                               \
        As[ar * ASTR + ak + 0] = to_tf32(t.x);                                 \
        As[ar * ASTR + ak + 1] = to_tf32(t.y);                                 \
        As[ar * ASTR + ak + 2] = to_tf32(t.z);                                 \
        As[ar * ASTR + ak + 3] = to_tf32(t.w);                                 \
        t = ra1;                                                               \
        As[(ar + 64) * ASTR + ak + 0] = to_tf32(t.x);                          \
        As[(ar + 64) * ASTR + ak + 1] = to_tf32(t.y);                          \
        As[(ar + 64) * ASTR + ak + 2] = to_tf32(t.z);                          \
        As[(ar + 64) * ASTR + ak + 3] = to_tf32(t.w);                          \
        t = rb0;                                                               \
        Bs[br * BSTR + bn + 0] = to_tf32(t.x);                                 \
        Bs[br * BSTR + bn + 1] = to_tf32(t.y);                                 \
        Bs[br * BSTR + bn + 2] = to_tf32(t.z);                                 \
        Bs[br * BSTR + bn + 3] = to_tf32(t.w);                                 \
        t = rb1;                                                               \
        Bs[(br + 8) * BSTR + bn + 0] = to_tf32(t.x);                           \
        Bs[(br + 8) * BSTR + bn + 1] = to_tf32(t.y);                           \
        Bs[(br + 8) * BSTR + bn + 2] = to_tf32(t.z);                           \
        Bs[(br + 8) * BSTR + bn + 3] = to_tf32(t.w);                           \
    }

#define COMPUTE_TILE()                                                         \
    {                                                                          \
        _Pragma("unroll")                                                      \
        for (int ks = 0; ks < 2; ks++) {                                       \
            const int kk = ks * 8;                                             \
            float af[4][4], bf[4][2];                                          \
            _Pragma("unroll")                                                  \
            for (int mt = 0; mt < 4; mt++) {                                   \
                const int mr = wm * 64 + mt * 16;                              \
                af[mt][0] = As[(mr + g) * ASTR + kk + tg];                     \
                af[mt][1] = As[(mr + g + 8) * ASTR + kk + tg];                 \
                af[mt][2] = As[(mr + g) * ASTR + kk + tg + 4];                 \
                af[mt][3] = As[(mr + g + 8) * ASTR + kk + tg + 4];             \
            }                                                                  \
            _Pragma("unroll")                                                  \
            for (int nt = 0; nt < 4; nt++) {                                   \
                const int nc = wn * 32 + nt * 8 + g;                           \
                bf[nt][0] = Bs[(kk + tg) * BSTR + nc];                         \
                bf[nt][1] = Bs[(kk + tg + 4) * BSTR + nc];                     \
            }                                                                  \
            _Pragma("unroll")                                                  \
            for (int mt = 0; mt < 4; mt++)                                     \
                _Pragma("unroll")                                              \
                for (int nt = 0; nt < 4; nt++)                                 \
                    mma_tf32(acc[mt][nt], af[mt], bf[nt]);                     \
        }                                                                      \
    }

    STORE_STAGE();
    __syncthreads();

    for (int k0 = BK; k0 < K; k0 += BK) {
        ra0 = *(const float4*)&Ap[(long long)ar * K + k0 + ak];
        ra1 = *(const float4*)&Ap[(long long)(ar + 64) * K + k0 + ak];
        rb0 = *(const float4*)&Bp[(long long)(k0 + br) * N + bn];
        rb1 = *(const float4*)&Bp[(long long)(k0 + br + 8) * N + bn];
        COMPUTE_TILE();
        __syncthreads();
        STORE_STAGE();
        __syncthreads();
    }
    COMPUTE_TILE();

    // epilogue
#pragma unroll
    for (int mt = 0; mt < 4; mt++) {
#pragma unroll
        for (int nt = 0; nt < 4; nt++) {
            const int row = m0 + wm * 64 + mt * 16 + g;
            const int col = n0 + wn * 32 + nt * 8 + 2 * tg;
            const float b0 = bias[col], b1 = bias[col + 1];
            float v0 = acc[mt][nt][0] + b0;
            float v1 = acc[mt][nt][1] + b1;
            float v2 = acc[mt][nt][2] + b0;
            float v3 = acc[mt][nt][3] + b1;
            if (do_gelu) {
                v0 = gelu_exact(v0); v1 = gelu_exact(v1);
                v2 = gelu_exact(v2); v3 = gelu_exact(v3);
            }
            *(float2*)&C[(long long)row * N + col] = make_float2(v0, v1);
            *(float2*)&C[(long long)(row + 8) * N + col] = make_float2(v2, v3);
        }
    }
}

// ---------------------------------------------------------------------------
// QKV tf32 GEMM: logical B[K=1024, N=3072] with col c -> Wqkv[c/192][k][c%192]
// Output scattered into Q/K/V [B,H,S,DH].
// ---------------------------------------------------------------------------
__global__ void __launch_bounds__(256)
tf32_qkv_kernel(const float* __restrict__ A,
                const float* __restrict__ Wqkv,
                float* __restrict__ Qo,
                float* __restrict__ Ko,
                float* __restrict__ Vo)
{
    __shared__ float As[BM * ASTR];
    __shared__ float Bs[BK * BSTR];

    const int tid  = threadIdx.x;
    const int warp = tid >> 5, lane = tid & 31;
    const int wm = warp >> 2, wn = warp & 3;
    const int g = lane >> 2, tg = lane & 3;
    const int m0 = blockIdx.y * BM, n0 = blockIdx.x * BN;
    const int K = D_;

    const int ar = tid >> 2;
    const int ak = (tid & 3) * 4;
    const int br = tid >> 5;
    const int bn = lane * 4;

    // B column mapping (fixed per thread): col = n0 + bn (float4 stays in head)
    const int bcol = n0 + bn;
    const int bhead = bcol / 192;
    const int be = bcol % 192;
    const float* Bp = Wqkv + (long long)bhead * D_ * 192 + be;

    const float* Ap = A + (long long)m0 * K;

    float acc[4][4][4];
#pragma unroll
    for (int i = 0; i < 4; i++)
#pragma unroll
        for (int j = 0; j < 4; j++)
#pragma unroll
            for (int r = 0; r < 4; r++) acc[i][j][r] = 0.0f;

    float4 ra0, ra1, rb0, rb1;

    ra0 = *(const float4*)&Ap[(long long)ar * K + ak];
    ra1 = *(const float4*)&Ap[(long long)(ar + 64) * K + ak];
    rb0 = *(const float4*)&Bp[(long long)br * 192];
    rb1 = *(const float4*)&Bp[(long long)(br + 8) * 192];

    STORE_STAGE();
    __syncthreads();

    for (int k0 = BK; k0 < K; k0 += BK) {
        ra0 = *(const float4*)&Ap[(long long)ar * K + k0 + ak];
        ra1 = *(const float4*)&Ap[(long long)(ar + 64) * K + k0 + ak];
        rb0 = *(const float4*)&Bp[(long long)(k0 + br) * 192];
        rb1 = *(const float4*)&Bp[(long long)(k0 + br + 8) * 192];
        COMPUTE_TILE();
        __syncthreads();
        STORE_STAGE();
        __syncthreads();
    }
    COMPUTE_TILE();

    // epilogue: scatter to Q/K/V
#pragma unroll
    for (int mt = 0; mt < 4; mt++) {
#pragma unroll
        for (int nt = 0; nt < 4; nt++) {
            const int row = m0 + wm * 64 + mt * 16 + g;   // token index
            const int col = n0 + wn * 32 + nt * 8 + 2 * tg;
            const int head = col / 192;
            const int e = col % 192;
            float* dst = (e < 64) ? Qo : (e < 128) ? Ko : Vo;
            const int eo = e & 63;
            const int b = row >> 11, s = row & 2047;
            const long long base = (((long long)b * H_ + head) * S_ + s) * DH_ + eo;
            const long long base2 = (((long long)b * H_ + head) * S_ + (row + 8 < ((b + 1) << 11) ? s + 8 : s + 8)) * DH_ + eo;
            (void)base2;
            *(float2*)&dst[base] = make_float2(acc[mt][nt][0], acc[mt][nt][1]);
            // row+8 is in the same batch (tile rows are within one 128-block, 2048 % 128 == 0)
            *(float2*)&dst[base + 8LL * DH_] = make_float2(acc[mt][nt][2], acc[mt][nt][3]);
        }
    }
}

// ---------------------------------------------------------------------------
// Causal flash attention, fp32 (unchanged from round 1)
// ---------------------------------------------------------------------------
__global__ void flash_attn_kernel(const float* __restrict__ Q,
                                  const float* __restrict__ K,
                                  const float* __restrict__ V,
                                  float* __restrict__ O)
{
    extern __shared__ float sm[];
    float* Qs = sm;
    float* Ks = sm + 64 * 68;
    float* Vs = sm + 2 * 64 * 68;
    float* Ps = Ks;

    const int tid = threadIdx.x;
    const int it = blockIdx.x;
    const int bh = blockIdx.y;
    const int i0 = it * 64;
    const int tr = tid >> 4, tc = tid & 15;
    const int r0 = tr * 4, c0 = tc * 4;

    const float* Qg = Q + (long long)bh * S_ * DH_;
    const float* Kg = K + (long long)bh * S_ * DH_;
    const float* Vg = V + (long long)bh * S_ * DH_;

#pragma unroll
    for (int i = 0; i < 4; i++) {
        int f4 = tid + i * 256;
        int row = f4 >> 4, col = (f4 & 15) * 4;
        *(float4*)&Qs[row * 68 + col] = *(const float4*)&Qg[(i0 + row) * DH_ + col];
    }

    float o[4][4];
    float m[4], l[4];
#pragma unroll
    for (int i = 0; i < 4; i++) {
        m[i] = -1e30f; l[i] = 0.0f;
#pragma unroll
        for (int j = 0; j < 4; j++) o[i][j] = 0.0f;
    }

    for (int jt = 0; jt <= it; jt++) {
        const int j0 = jt * 64;
#pragma unroll
        for (int i = 0; i < 4; i++) {
            int f4 = tid + i * 256;
            int row = f4 >> 4, col = (f4 & 15) * 4;
            *(float4*)&Ks[row * 68 + col] = *(const float4*)&Kg[(j0 + row) * DH_ + col];
            *(float4*)&Vs[row * 68 + col] = *(const float4*)&Vg[(j0 + row) * DH_ + col];
        }
        __syncthreads();

        float s[4][4];
#pragma unroll
        for (int i = 0; i < 4; i++)
#pragma unroll
            for (int j = 0; j < 4; j++) s[i][j] = 0.0f;

        for (int d = 0; d < 64; d += 4) {
            float4 qv[4], kv[4];
#pragma unroll
            for (int i = 0; i < 4; i++) qv[i] = *(float4*)&Qs[(r0 + i) * 68 + d];
#pragma unroll
            for (int j = 0; j < 4; j++) kv[j] = *(float4*)&Ks[(c0 + j) * 68 + d];
#pragma unroll
            for (int i = 0; i < 4; i++)
#pragma unroll
                for (int j = 0; j < 4; j++)
                    s[i][j] += qv[i].x * kv[j].x + qv[i].y * kv[j].y +
                               qv[i].z * kv[j].z + qv[i].w * kv[j].w;
        }

#pragma unroll
        for (int i = 0; i < 4; i++)
#pragma unroll
            for (int j = 0; j < 4; j++) {
                float v = s[i][j] * 0.125f;
                if (j0 + c0 + j > i0 + r0 + i) v = -1e30f;
                s[i][j] = v;
            }

        float p[4][4];
#pragma unroll
        for (int i = 0; i < 4; i++) {
            float rm = fmaxf(fmaxf(s[i][0], s[i][1]), fmaxf(s[i][2], s[i][3]));
#pragma unroll
            for (int off = 1; off <= 8; off <<= 1)
                rm = fmaxf(rm, __shfl_xor_sync(0xffffffffu, rm, off));
            float mn = fmaxf(m[i], rm);
            float corr = __expf(m[i] - mn);
            float rs = 0.0f;
#pragma unroll
            for (int j = 0; j < 4; j++) {
                p[i][j] = __expf(s[i][j] - mn);
                rs += p[i][j];
            }
#pragma unroll
            for (int off = 1; off <= 8; off <<= 1)
                rs += __shfl_xor_sync(0xffffffffu, rs, off);
            l[i] = l[i] * corr + rs;
            m[i] = mn;
#pragma unroll
            for (int j = 0; j < 4; j++) o[i][j] *= corr;
        }

        __syncthreads();
#pragma unroll
        for (int i = 0; i < 4; i++)
#pragma unroll
            for (int j = 0; j < 4; j++)
                Ps[(r0 + i) * 68 + c0 + j] = p[i][j];
        __syncthreads();

        for (int c4 = 0; c4 < 64; c4 += 4) {
            float4 pv[4], vv[4];
#pragma unroll
            for (int i = 0; i < 4; i++) pv[i] = *(float4*)&Ps[(r0 + i) * 68 + c4];
#pragma unroll
            for (int j = 0; j < 4; j++) vv[j] = *(float4*)&Vs[(c4 + j) * 68 + tc * 4];
#pragma unroll
            for (int i = 0; i < 4; i++) {
                o[i][0] += pv[i].x * vv[0].x + pv[i].y * vv[1].x + pv[i].z * vv[2].x + pv[i].w * vv[3].x;
                o[i][1] += pv[i].x * vv[0].y + pv[i].y * vv[1].y + pv[i].z * vv[2].y + pv[i].w * vv[3].y;
                o[i][2] += pv[i].x * vv[0].z + pv[i].y * vv[1].z + pv[i].z * vv[2].z + pv[i].w * vv[3].z;
                o[i][3] += pv[i].x * vv[0].w + pv[i].y * vv[1].w + pv[i].z * vv[2].w + pv[i].w * vv[3].w;
            }
        }
        __syncthreads();
    }

    const int b = bh >> 4, h = bh & 15;
#pragma unroll
    for (int i = 0; i < 4; i++) {
        float inv = 1.0f / l[i];
        float4 v = make_float4(o[i][0] * inv, o[i][1] * inv, o[i][2] * inv, o[i][3] * inv);
        *(float4*)&O[((long long)(b * S_ + i0 + r0 + i)) * D_ + h * 64 + tc * 4] = v;
    }
}

// ---------------------------------------------------------------------------
// Fused residual + LayerNorm (unchanged)
// ---------------------------------------------------------------------------
__global__ void ln_kernel(const float* __restrict__ A,
                          const float* __restrict__ R,
                          const float* __restrict__ G,
                          const float* __restrict__ Be,
                          float* __restrict__ Out)
{
    const int row = blockIdx.x;
    const int tid = threadIdx.x;
    const long long base = (long long)row * D_;

    float4 va = *(const float4*)&A[base + tid * 4];
    float4 vb = *(const float4*)&R[base + tid * 4];
    float4 v = make_float4(va.x + vb.x, va.y + vb.y, va.z + vb.z, va.w + vb.w);

    float s = v.x + v.y + v.z + v.w;
    float ss = v.x * v.x + v.y * v.y + v.z * v.z + v.w * v.w;

    __shared__ float rs_[8], rss_[8];
#pragma unroll
    for (int off = 16; off >= 1; off >>= 1) {
        s += __shfl_xor_sync(0xffffffffu, s, off);
        ss += __shfl_xor_sync(0xffffffffu, ss, off);
    }
    int warp = tid >> 5, lane = tid & 31;
    if (lane == 0) { rs_[warp] = s; rss_[warp] = ss; }
    __syncthreads();
    if (warp == 0) {
        s = (lane < 8) ? rs_[lane] : 0.0f;
        ss = (lane < 8) ? rss_[lane] : 0.0f;
#pragma unroll
        for (int off = 4; off >= 1; off >>= 1) {
            s += __shfl_xor_sync(0xffffffffu, s, off);
            ss += __shfl_xor_sync(0xffffffffu, ss, off);
        }
        if (lane == 0) { rs_[0] = s; rss_[0] = ss; }
    }
    __syncthreads();
    s = rs_[0]; ss = rss_[0];

    const float mu = s * (1.0f / 1024.0f);
    const float var = ss * (1.0f / 1024.0f) - mu * mu;
    const float rstd = rsqrtf(var + 1e-5f);

    float4 g4 = *(const float4*)&G[tid * 4];
    float4 b4 = *(const float4*)&Be[tid * 4];
    float4 ov;
    ov.x = (v.x - mu) * rstd * g4.x + b4.x;
    ov.y = (v.y - mu) * rstd * g4.y + b4.y;
    ov.z = (v.z - mu) * rstd * g4.z + b4.z;
    ov.w = (v.w - mu) * rstd * g4.w + b4.w;
    *(float4*)&Out[base + tid * 4] = ov;
}

// ---------------------------------------------------------------------------
extern "C" void kernel_launch(void* const* d_in, const int* in_sizes, int n_in,
                              void* d_out, int out_size)
{
    (void)in_sizes; (void)n_in; (void)out_size;
    const float* x     = (const float*)d_in[0];
    const float* Wqkv  = (const float*)d_in[1];
    const float* Wproj = (const float*)d_in[2];
    const float* bproj = (const float*)d_in[3];
    const float* ln1g  = (const float*)d_in[4];
    const float* ln1b  = (const float*)d_in[5];
    const float* ln2g  = (const float*)d_in[6];
    const float* ln2b  = (const float*)d_in[7];
    const float* W1    = (const float*)d_in[8];
    const float* b1    = (const float*)d_in[9];
    const float* W2    = (const float*)d_in[10];
    const float* b2    = (const float*)d_in[11];
    float* out = (float*)d_out;

    float* scratch = nullptr;
    cudaGetSymbolAddress((void**)&scratch, g_scratch);

    float* Qb   = scratch + OFF_Q;
    float* Kb   = scratch + OFF_K;
    float* Vb   = scratch + OFF_V;
    float* ATT  = scratch + OFF_ATT;
    float* PROJ = scratch + OFF_PROJ;
    float* LN1  = scratch + OFF_LN1;
    float* FFH  = scratch + OFF_FFH;
    float* MLP  = scratch + OFF_MLP;

    // 1) QKV projection (tf32 tensor cores)
    tf32_qkv_kernel<<<dim3(24, 64), 256>>>(x, Wqkv, Qb, Kb, Vb);

    // 2) causal flash attention (fp32)
    const int smem = 3 * 64 * 68 * (int)sizeof(float);
    cudaFuncSetAttribute(flash_attn_kernel,
                         cudaFuncAttributeMaxDynamicSharedMemorySize, smem);
    flash_attn_kernel<<<dim3(32, 64), 256, smem>>>(Qb, Kb, Vb, ATT);

    // 3) output projection + bias
    tf32_gemm_kernel<<<dim3(8, 64), 256>>>(ATT, Wproj, bproj, PROJ, 1024, 1024, 0);

    // 4) residual + LN1
    ln_kernel<<<8192, 256>>>(x, PROJ, ln1g, ln1b, LN1);

    // 5) MLP up + bias + exact GELU
    tf32_gemm_kernel<<<dim3(32, 64), 256>>>(LN1, W1, b1, FFH, 4096, 1024, 1);

    // 6) MLP down + bias
    tf32_gemm_kernel<<<dim3(8, 64), 256>>>(FFH, W2, b2, MLP, 1024, 4096, 0);

    // 7) residual + LN2 -> output
    ln_kernel<<<8192, 256>>>(LN1, MLP, ln2g, ln2b, out);
}

// round 3
// speedup vs baseline: 3.2304x; 1.6806x over previous
#include <cuda_runtime.h>
#include <math.h>

// Problem constants
#define B_ 4
#define S_ 2048
#define D_ 1024
#define H_ 16
#define DH_ 64
#define DFF_ 4096

// Scratch layout (floats)
#define OFF_Q    0LL
#define OFF_K    8388608LL
#define OFF_V    16777216LL
#define OFF_ATT  25165824LL
#define OFF_PROJ 33554432LL
#define OFF_LN1  41943040LL
#define OFF_FFH  50331648LL
#define OFF_MLP  83886080LL
#define SCRATCH_TOTAL 92274688LL

__device__ float g_scratch[SCRATCH_TOTAL];

// ---------------------------------------------------------------------------
// tf32 mma.sync helpers
// ---------------------------------------------------------------------------
__device__ __forceinline__ float to_tf32(float x) {
    float y;
    asm("cvt.rna.tf32.f32 %0, %1;" : "=f"(y) : "f"(x));
    return y;
}

__device__ __forceinline__ void mma_tf32(float c[4], const float a[4], const float b[2]) {
    asm volatile(
        "mma.sync.aligned.m16n8k8.row.col.f32.tf32.tf32.f32 "
        "{%0,%1,%2,%3}, {%4,%5,%6,%7}, {%8,%9}, {%0,%1,%2,%3};"
        : "+f"(c[0]), "+f"(c[1]), "+f"(c[2]), "+f"(c[3])
        : "r"(__float_as_uint(a[0])), "r"(__float_as_uint(a[1])),
          "r"(__float_as_uint(a[2])), "r"(__float_as_uint(a[3])),
          "r"(__float_as_uint(b[0])), "r"(__float_as_uint(b[1])));
}

__device__ __forceinline__ float gelu_exact(float x) {
    return 0.5f * x * (1.0f + erff(x * 0.70710678118654752f));
}

// ---------------------------------------------------------------------------
// Generic tf32 tensor-core GEMM: C[M,N] = A[M,K] @ B[K,N] + bias (+ GELU)
// BM=128 BN=128 BK=16, 256 threads (8 warps, 2x4), warp tile 64x32.
// ---------------------------------------------------------------------------
#define BM 128
#define BN 128
#define BK 16
#define ASTR 20
#define BSTR 136

__global__ void __launch_bounds__(256)
tf32_gemm_kernel(const float* __restrict__ A,
                 const float* __restrict__ Bm,
                 const float* __restrict__ bias,
                 float* __restrict__ C,
                 int N, int K, int do_gelu)
{
    __shared__ float As[BM * ASTR];
    __shared__ float Bs[BK * BSTR];

    const int tid  = threadIdx.x;
    const int warp = tid >> 5, lane = tid & 31;
    const int wm = warp >> 2, wn = warp & 3;
    const int g = lane >> 2, tg = lane & 3;
    const int m0 = blockIdx.y * BM, n0 = blockIdx.x * BN;

    const int ar = tid >> 2;
    const int ak = (tid & 3) * 4;
    const int br = tid >> 5;
    const int bn = (lane) * 4;

    const float* Ap = A + (long long)m0 * K;
    const float* Bp = Bm + n0;

    float acc[4][4][4];
#pragma unroll
    for (int i = 0; i < 4; i++)
#pragma unroll
        for (int j = 0; j < 4; j++)
#pragma unroll
            for (int r = 0; r < 4; r++) acc[i][j][r] = 0.0f;

    float4 ra0, ra1, rb0, rb1;

    ra0 = *(const float4*)&Ap[(long long)ar * K + ak];
    ra1 = *(const float4*)&Ap[(long long)(ar + 64) * K + ak];
    rb0 = *(const float4*)&Bp[(long long)br * N + bn];
    rb1 = *(const float4*)&Bp[(long long)(br + 8) * N + bn];

#define STORE_STAGE()                                                          \
    {                                                                          \
        float4 t;                                                              \
        t = ra0;                                                               \
        As[ar * ASTR + ak + 0] = to_tf32(t.x);                                 \
        As[ar * ASTR + ak + 1] = to_tf32(t.y);                                 \
        As[ar * ASTR + ak + 2] = to_tf32(t.z);                                 \
        As[ar * ASTR + ak + 3] = to_tf32(t.w);                                 \
        t = ra1;                                                               \
        As[(ar + 64) * ASTR + ak + 0] = to_tf32(t.x);                          \
        As[(ar + 64) * ASTR + ak + 1] = to_tf32(t.y);                          \
        As[(ar + 64) * ASTR + ak + 2] = to_tf32(t.z);                          \
        As[(ar + 64) * ASTR + ak + 3] = to_tf32(t.w);                          \
        t = rb0;                                                               \
        Bs[br * BSTR + bn + 0] = to_tf32(t.x);                                 \
        Bs[br * BSTR + bn + 1] = to_tf32(t.y);                                 \
        Bs[br * BSTR + bn + 2] = to_tf32(t.z);                                 \
        Bs[br * BSTR + bn + 3] = to_tf32(t.w);                                 \
        t = rb1;                                                               \
        Bs[(br + 8) * BSTR + bn + 0] = to_tf32(t.x);                           \
        Bs[(br + 8) * BSTR + bn + 1] = to_tf32(t.y);                           \
        Bs[(br + 8) * BSTR + bn + 2] = to_tf32(t.z);                           \
        Bs[(br + 8) * BSTR + bn + 3] = to_tf32(t.w);                           \
    }

#define COMPUTE_TILE()                                                         \
    {                                                                          \
        _Pragma("unroll")                                                      \
        for (int ks = 0; ks < 2; ks++) {                                       \
            const int kk = ks * 8;                                             \
            float af[4][4], bf[4][2];                                          \
            _Pragma("unroll")                                                  \
            for (int mt = 0; mt < 4; mt++) {                                   \
                const int mr = wm * 64 + mt * 16;                              \
                af[mt][0] = As[(mr + g) * ASTR + kk + tg];                     \
                af[mt][1] = As[(mr + g + 8) * ASTR + kk + tg];                 \
                af[mt][2] = As[(mr + g) * ASTR + kk + tg + 4];                 \
                af[mt][3] = As[(mr + g + 8) * ASTR + kk + tg + 4];             \
            }                                                                  \
            _Pragma("unroll")                                                  \
            for (int nt = 0; nt < 4; nt++) {                                   \
                const int nc = wn * 32 + nt * 8 + g;                           \
                bf[nt][0] = Bs[(kk + tg) * BSTR + nc];                         \
                bf[nt][1] = Bs[(kk + tg + 4) * BSTR + nc];                     \
            }                                                                  \
            _Pragma("unroll")                                                  \
            for (int mt = 0; mt < 4; mt++)                                     \
                _Pragma("unroll")                                              \
                for (int nt = 0; nt < 4; nt++)                                 \
                    mma_tf32(acc[mt][nt], af[mt], bf[nt]);                     \
        }                                                                      \
    }

    STORE_STAGE();
    __syncthreads();

    for (int k0 = BK; k0 < K; k0 += BK) {
        ra0 = *(const float4*)&Ap[(long long)ar * K + k0 + ak];
        ra1 = *(const float4*)&Ap[(long long)(ar + 64) * K + k0 + ak];
        rb0 = *(const float4*)&Bp[(long long)(k0 + br) * N + bn];
        rb1 = *(const float4*)&Bp[(long long)(k0 + br + 8) * N + bn];
        COMPUTE_TILE();
        __syncthreads();
        STORE_STAGE();
        __syncthreads();
    }
    COMPUTE_TILE();

#pragma unroll
    for (int mt = 0; mt < 4; mt++) {
#pragma unroll
        for (int nt = 0; nt < 4; nt++) {
            const int row = m0 + wm * 64 + mt * 16 + g;
            const int col = n0 + wn * 32 + nt * 8 + 2 * tg;
            const float b0 = bias[col], b1 = bias[col + 1];
            float v0 = acc[mt][nt][0] + b0;
            float v1 = acc[mt][nt][1] + b1;
            float v2 = acc[mt][nt][2] + b0;
            float v3 = acc[mt][nt][3] + b1;
            if (do_gelu) {
                v0 = gelu_exact(v0); v1 = gelu_exact(v1);
                v2 = gelu_exact(v2); v3 = gelu_exact(v3);
            }
            *(float2*)&C[(long long)row * N + col] = make_float2(v0, v1);
            *(float2*)&C[(long long)(row + 8) * N + col] = make_float2(v2, v3);
        }
    }
}

// ---------------------------------------------------------------------------
// QKV tf32 GEMM (unchanged from round 2)
// ---------------------------------------------------------------------------
__global__ void __launch_bounds__(256)
tf32_qkv_kernel(const float* __restrict__ A,
                const float* __restrict__ Wqkv,
                float* __restrict__ Qo,
                float* __restrict__ Ko,
                float* __restrict__ Vo)
{
    __shared__ float As[BM * ASTR];
    __shared__ float Bs[BK * BSTR];

    const int tid  = threadIdx.x;
    const int warp = tid >> 5, lane = tid & 31;
    const int wm = warp >> 2, wn = warp & 3;
    const int g = lane >> 2, tg = lane & 3;
    const int m0 = blockIdx.y * BM, n0 = blockIdx.x * BN;
    const int K = D_;

    const int ar = tid >> 2;
    const int ak = (tid & 3) * 4;
    const int br = tid >> 5;
    const int bn = lane * 4;

    const int bcol = n0 + bn;
    const int bhead = bcol / 192;
    const int be = bcol % 192;
    const float* Bp = Wqkv + (long long)bhead * D_ * 192 + be;

    const float* Ap = A + (long long)m0 * K;

    float acc[4][4][4];
#pragma unroll
    for (int i = 0; i < 4; i++)
#pragma unroll
        for (int j = 0; j < 4; j++)
#pragma unroll
            for (int r = 0; r < 4; r++) acc[i][j][r] = 0.0f;

    float4 ra0, ra1, rb0, rb1;

    ra0 = *(const float4*)&Ap[(long long)ar * K + ak];
    ra1 = *(const float4*)&Ap[(long long)(ar + 64) * K + ak];
    rb0 = *(const float4*)&Bp[(long long)br * 192];
    rb1 = *(const float4*)&Bp[(long long)(br + 8) * 192];

    STORE_STAGE();
    __syncthreads();

    for (int k0 = BK; k0 < K; k0 += BK) {
        ra0 = *(const float4*)&Ap[(long long)ar * K + k0 + ak];
        ra1 = *(const float4*)&Ap[(long long)(ar + 64) * K + k0 + ak];
        rb0 = *(const float4*)&Bp[(long long)(k0 + br) * 192];
        rb1 = *(const float4*)&Bp[(long long)(k0 + br + 8) * 192];
        COMPUTE_TILE();
        __syncthreads();
        STORE_STAGE();
        __syncthreads();
    }
    COMPUTE_TILE();

#pragma unroll
    for (int mt = 0; mt < 4; mt++) {
#pragma unroll
        for (int nt = 0; nt < 4; nt++) {
            const int row = m0 + wm * 64 + mt * 16 + g;
            const int col = n0 + wn * 32 + nt * 8 + 2 * tg;
            const int head = col / 192;
            const int e = col % 192;
            float* dst = (e < 64) ? Qo : (e < 128) ? Ko : Vo;
            const int eo = e & 63;
            const int b = row >> 11, s = row & 2047;
            const long long base = (((long long)b * H_ + head) * S_ + s) * DH_ + eo;
            *(float2*)&dst[base] = make_float2(acc[mt][nt][0], acc[mt][nt][1]);
            *(float2*)&dst[base + 8LL * DH_] = make_float2(acc[mt][nt][2], acc[mt][nt][3]);
        }
    }
}

// ---------------------------------------------------------------------------
// Causal flash attention on tf32 tensor cores.
// Block: 128 query rows for one (b,h); 8 warps, each owns a 16-row m-tile.
// K-tiles of 64. Smem: Q[128x68], K[64x68], V[64x72], P[8 x 16x68].
// ---------------------------------------------------------------------------
__global__ void __launch_bounds__(256)
flash_attn_tc_kernel(const float* __restrict__ Q,
                     const float* __restrict__ K,
                     const float* __restrict__ V,
                     float* __restrict__ O)
{
    extern __shared__ float sm[];
    float* Qs = sm;                        // 128 x 68
    float* Ks = Qs + 128 * 68;             // 64 x 68
    float* Vs = Ks + 64 * 68;              // 64 x 72
    float* Ps = Vs + 64 * 72;              // 8 warps x 16 x 68

    const int tid = threadIdx.x;
    const int warp = tid >> 5, lane = tid & 31;
    const int g = lane >> 2, tg = lane & 3;
    const int i0 = blockIdx.x * 128;
    const int bh = blockIdx.y;

    const float* Qg = Q + (long long)bh * S_ * DH_;
    const float* Kg = K + (long long)bh * S_ * DH_;
    const float* Vg = V + (long long)bh * S_ * DH_;

    // load Q tile (scaled by softmax scale, converted to tf32)
#pragma unroll
    for (int i = 0; i < 8; i++) {
        int idx = tid + i * 256;
        int row = idx >> 4, col = (idx & 15) * 4;
        float4 v = *(const float4*)&Qg[(long long)(i0 + row) * DH_ + col];
        Qs[row * 68 + col + 0] = to_tf32(v.x * 0.125f);
        Qs[row * 68 + col + 1] = to_tf32(v.y * 0.125f);
        Qs[row * 68 + col + 2] = to_tf32(v.z * 0.125f);
        Qs[row * 68 + col + 3] = to_tf32(v.w * 0.125f);
    }

    float oacc[8][4];
#pragma unroll
    for (int nt = 0; nt < 8; nt++)
#pragma unroll
        for (int r = 0; r < 4; r++) oacc[nt][r] = 0.0f;

    float m0 = -1e30f, m1 = -1e30f, l0 = 0.0f, l1 = 0.0f;

    const int wrow0 = i0 + warp * 16;       // warp's first query row (global)
    const int jtmax = (i0 + 127) >> 6;
    float* Pw = Ps + warp * 16 * 68;

    for (int jt = 0; jt <= jtmax; jt++) {
        const int j0 = jt << 6;
        __syncthreads();   // previous tile fully consumed (also covers Q stores)
        // load K/V tiles (tf32)
#pragma unroll
        for (int i = 0; i < 4; i++) {
            int idx = tid + i * 256;
            int row = idx >> 4, col = (idx & 15) * 4;
            float4 kv = *(const float4*)&Kg[(long long)(j0 + row) * DH_ + col];
            Ks[row * 68 + col + 0] = to_tf32(kv.x);
            Ks[row * 68 + col + 1] = to_tf32(kv.y);
            Ks[row * 68 + col + 2] = to_tf32(kv.z);
            Ks[row * 68 + col + 3] = to_tf32(kv.w);
            float4 vv = *(const float4*)&Vg[(long long)(j0 + row) * DH_ + col];
            Vs[row * 72 + col + 0] = to_tf32(vv.x);
            Vs[row * 72 + col + 1] = to_tf32(vv.y);
            Vs[row * 72 + col + 2] = to_tf32(vv.z);
            Vs[row * 72 + col + 3] = to_tf32(vv.w);
        }
        __syncthreads();

        if (j0 > wrow0 + 15) continue;      // fully beyond causal horizon for this warp

        // S = Q . K^T  (warp 16x64 via 8 n-tiles x 8 k-chunks)
        float sacc[8][4];
#pragma unroll
        for (int nt = 0; nt < 8; nt++)
#pragma unroll
            for (int r = 0; r < 4; r++) sacc[nt][r] = 0.0f;

#pragma unroll
        for (int kc = 0; kc < 8; kc++) {
            const int kk = kc * 8;
            float af[4];
            af[0] = Qs[(warp * 16 + g) * 68 + kk + tg];
            af[1] = Qs[(warp * 16 + g + 8) * 68 + kk + tg];
            af[2] = Qs[(warp * 16 + g) * 68 + kk + tg + 4];
            af[3] = Qs[(warp * 16 + g + 8) * 68 + kk + tg + 4];
#pragma unroll
            for (int nt = 0; nt < 8; nt++) {
                float bf[2];
                bf[0] = Ks[(nt * 8 + g) * 68 + kk + tg];
                bf[1] = Ks[(nt * 8 + g) * 68 + kk + tg + 4];
                mma_tf32(sacc[nt], af, bf);
            }
        }

        // causal mask (only needed on diagonal tiles)
        if (j0 + 63 > wrow0) {
            const int row0 = wrow0 + g, row1 = wrow0 + 8 + g;
#pragma unroll
            for (int nt = 0; nt < 8; nt++) {
                const int c0 = j0 + nt * 8 + 2 * tg;
                if (c0 > row0)     sacc[nt][0] = -1e30f;
                if (c0 + 1 > row0) sacc[nt][1] = -1e30f;
                if (c0 > row1)     sacc[nt][2] = -1e30f;
                if (c0 + 1 > row1) sacc[nt][3] = -1e30f;
            }
        }

        // online softmax (rows g and g+8)
        float rm0 = -1e30f, rm1 = -1e30f;
#pragma unroll
        for (int nt = 0; nt < 8; nt++) {
            rm0 = fmaxf(rm0, fmaxf(sacc[nt][0], sacc[nt][1]));
            rm1 = fmaxf(rm1, fmaxf(sacc[nt][2], sacc[nt][3]));
        }
        rm0 = fmaxf(rm0, __shfl_xor_sync(0xffffffffu, rm0, 1));
        rm0 = fmaxf(rm0, __shfl_xor_sync(0xffffffffu, rm0, 2));
        rm1 = fmaxf(rm1, __shfl_xor_sync(0xffffffffu, rm1, 1));
        rm1 = fmaxf(rm1, __shfl_xor_sync(0xffffffffu, rm1, 2));

        const float mn0 = fmaxf(m0, rm0), mn1 = fmaxf(m1, rm1);
        const float cr0 = __expf(m0 - mn0), cr1 = __expf(m1 - mn1);
        float rs0 = 0.0f, rs1 = 0.0f;
#pragma unroll
        for (int nt = 0; nt < 8; nt++) {
            float p0 = to_tf32(__expf(sacc[nt][0] - mn0));
            float p1 = to_tf32(__expf(sacc[nt][1] - mn0));
            float p2 = to_tf32(__expf(sacc[nt][2] - mn1));
            float p3 = to_tf32(__expf(sacc[nt][3] - mn1));
            rs0 += p0 + p1;
            rs1 += p2 + p3;
            sacc[nt][0] = p0; sacc[nt][1] = p1;
            sacc[nt][2] = p2; sacc[nt][3] = p3;
        }
        rs0 += __shfl_xor_sync(0xffffffffu, rs0, 1);
        rs0 += __shfl_xor_sync(0xffffffffu, rs0, 2);
        rs1 += __shfl_xor_sync(0xffffffffu, rs1, 1);
        rs1 += __shfl_xor_sync(0xffffffffu, rs1, 2);

        l0 = l0 * cr0 + rs0;
        l1 = l1 * cr1 + rs1;
        m0 = mn0; m1 = mn1;

#pragma unroll
        for (int nt = 0; nt < 8; nt++) {
            oacc[nt][0] *= cr0; oacc[nt][1] *= cr0;
            oacc[nt][2] *= cr1; oacc[nt][3] *= cr1;
        }

        // reshape P: C-frag -> warp-private smem -> A-frag
        __syncwarp();
#pragma unroll
        for (int nt = 0; nt < 8; nt++) {
            *(float2*)&Pw[g * 68 + nt * 8 + 2 * tg] =
                make_float2(sacc[nt][0], sacc[nt][1]);
            *(float2*)&Pw[(g + 8) * 68 + nt * 8 + 2 * tg] =
                make_float2(sacc[nt][2], sacc[nt][3]);
        }
        __syncwarp();

        // O += P . V
#pragma unroll
        for (int kc = 0; kc < 8; kc++) {
            const int kk = kc * 8;
            float af[4];
            af[0] = Pw[g * 68 + kk + tg];
            af[1] = Pw[(g + 8) * 68 + kk + tg];
            af[2] = Pw[g * 68 + kk + tg + 4];
            af[3] = Pw[(g + 8) * 68 + kk + tg + 4];
#pragma unroll
            for (int nt = 0; nt < 8; nt++) {
                float bf[2];
                bf[0] = Vs[(kk + tg) * 72 + nt * 8 + g];
                bf[1] = Vs[(kk + tg + 4) * 72 + nt * 8 + g];
                mma_tf32(oacc[nt], af, bf);
            }
        }
    }

    // epilogue: heads concatenated -> att[(b*S+s)*D + h*64 + d]
    const int b = bh >> 4, h = bh & 15;
    const float inv0 = 1.0f / l0, inv1 = 1.0f / l1;
    const int row0 = wrow0 + g, row1 = wrow0 + 8 + g;
#pragma unroll
    for (int nt = 0; nt < 8; nt++) {
        const int col = h * 64 + nt * 8 + 2 * tg;
        *(float2*)&O[(long long)(b * S_ + row0) * D_ + col] =
            make_float2(oacc[nt][0] * inv0, oacc[nt][1] * inv0);
        *(float2*)&O[(long long)(b * S_ + row1) * D_ + col] =
            make_float2(oacc[nt][2] * inv1, oacc[nt][3] * inv1);
    }
}

// ---------------------------------------------------------------------------
// Fused residual + LayerNorm (unchanged)
// ---------------------------------------------------------------------------
__global__ void ln_kernel(const float* __restrict__ A,
                          const float* __restrict__ R,
                          const float* __restrict__ G,
                          const float* __restrict__ Be,
                          float* __restrict__ Out)
{
    const int row = blockIdx.x;
    const int tid = threadIdx.x;
    const long long base = (long long)row * D_;

    float4 va = *(const float4*)&A[base + tid * 4];
    float4 vb = *(const float4*)&R[base + tid * 4];
    float4 v = make_float4(va.x + vb.x, va.y + vb.y, va.z + vb.z, va.w + vb.w);

    float s = v.x + v.y + v.z + v.w;
    float ss = v.x * v.x + v.y * v.y + v.z * v.z + v.w * v.w;

    __shared__ float rs_[8], rss_[8];
#pragma unroll
    for (int off = 16; off >= 1; off >>= 1) {
        s += __shfl_xor_sync(0xffffffffu, s, off);
        ss += __shfl_xor_sync(0xffffffffu, ss, off);
    }
    int warp = tid >> 5, lane = tid & 31;
    if (lane == 0) { rs_[warp] = s; rss_[warp] = ss; }
    __syncthreads();
    if (warp == 0) {
        s = (lane < 8) ? rs_[lane] : 0.0f;
        ss = (lane < 8) ? rss_[lane] : 0.0f;
#pragma unroll
        for (int off = 4; off >= 1; off >>= 1) {
            s += __shfl_xor_sync(0xffffffffu, s, off);
            ss += __shfl_xor_sync(0xffffffffu, ss, off);
        }
        if (lane == 0) { rs_[0] = s; rss_[0] = ss; }
    }
    __syncthreads();
    s = rs_[0]; ss = rss_[0];

    const float mu = s * (1.0f / 1024.0f);
    const float var = ss * (1.0f / 1024.0f) - mu * mu;
    const float rstd = rsqrtf(var + 1e-5f);

    float4 g4 = *(const float4*)&G[tid * 4];
    float4 b4 = *(const float4*)&Be[tid * 4];
    float4 ov;
    ov.x = (v.x - mu) * rstd * g4.x + b4.x;
    ov.y = (v.y - mu) * rstd * g4.y + b4.y;
    ov.z = (v.z - mu) * rstd * g4.z + b4.z;
    ov.w = (v.w - mu) * rstd * g4.w + b4.w;
    *(float4*)&Out[base + tid * 4] = ov;
}

// ---------------------------------------------------------------------------
extern "C" void kernel_launch(void* const* d_in, const int* in_sizes, int n_in,
                              void* d_out, int out_size)
{
    (void)in_sizes; (void)n_in; (void)out_size;
    const float* x     = (const float*)d_in[0];
    const float* Wqkv  = (const float*)d_in[1];
    const float* Wproj = (const float*)d_in[2];
    const float* bproj = (const float*)d_in[3];
    const float* ln1g  = (const float*)d_in[4];
    const float* ln1b  = (const float*)d_in[5];
    const float* ln2g  = (const float*)d_in[6];
    const float* ln2b  = (const float*)d_in[7];
    const float* W1    = (const float*)d_in[8];
    const float* b1    = (const float*)d_in[9];
    const float* W2    = (const float*)d_in[10];
    const float* b2    = (const float*)d_in[11];
    float* out = (float*)d_out;

    float* scratch = nullptr;
    cudaGetSymbolAddress((void**)&scratch, g_scratch);

    float* Qb   = scratch + OFF_Q;
    float* Kb   = scratch + OFF_K;
    float* Vb   = scratch + OFF_V;
    float* ATT  = scratch + OFF_ATT;
    float* PROJ = scratch + OFF_PROJ;
    float* LN1  = scratch + OFF_LN1;
    float* FFH  = scratch + OFF_FFH;
    float* MLP  = scratch + OFF_MLP;

    // 1) QKV projection (tf32 tensor cores)
    tf32_qkv_kernel<<<dim3(24, 64), 256>>>(x, Wqkv, Qb, Kb, Vb);

    // 2) causal flash attention (tf32 tensor cores)
    const int fa_smem = (128 * 68 + 64 * 68 + 64 * 72 + 8 * 16 * 68) * (int)sizeof(float);
    cudaFuncSetAttribute(flash_attn_tc_kernel,
                         cudaFuncAttributeMaxDynamicSharedMemorySize, fa_smem);
    flash_attn_tc_kernel<<<dim3(16, 64), 256, fa_smem>>>(Qb, Kb, Vb, ATT);

    // 3) output projection + bias
    tf32_gemm_kernel<<<dim3(8, 64), 256>>>(ATT, Wproj, bproj, PROJ, 1024, 1024, 0);

    // 4) residual + LN1
    ln_kernel<<<8192, 256>>>(x, PROJ, ln1g, ln1b, LN1);

    // 5) MLP up + bias + exact GELU
    tf32_gemm_kernel<<<dim3(32, 64), 256>>>(LN1, W1, b1, FFH, 4096, 1024, 1);

    // 6) MLP down + bias
    tf32_gemm_kernel<<<dim3(8, 64), 256>>>(FFH, W2, b2, MLP, 1024, 4096, 0);

    // 7) residual + LN2 -> output
    ln_kernel<<<8192, 256>>>(LN1, MLP, ln2g, ln2b, out);
}

// round 4
// speedup vs baseline: 3.6063x; 1.1164x over previous
#include <cuda_runtime.h>
#include <math.h>

// Problem constants
#define B_ 4
#define S_ 2048
#define D_ 1024
#define H_ 16
#define DH_ 64
#define DFF_ 4096

// Scratch layout (floats)
#define OFF_Q    0LL
#define OFF_K    8388608LL
#define OFF_V    16777216LL
#define OFF_ATT  25165824LL
#define OFF_PROJ 33554432LL
#define OFF_LN1  41943040LL
#define OFF_FFH  50331648LL
#define OFF_MLP  83886080LL
#define SCRATCH_TOTAL 92274688LL

__device__ float g_scratch[SCRATCH_TOTAL];

// ---------------------------------------------------------------------------
// helpers
// ---------------------------------------------------------------------------
__device__ __forceinline__ float to_tf32(float x) {
    float y;
    asm("cvt.rna.tf32.f32 %0, %1;" : "=f"(y) : "f"(x));
    return y;
}

__device__ __forceinline__ void mma_tf32(float c[4], const float a[4], const float b[2]) {
    asm volatile(
        "mma.sync.aligned.m16n8k8.row.col.f32.tf32.tf32.f32 "
        "{%0,%1,%2,%3}, {%4,%5,%6,%7}, {%8,%9}, {%0,%1,%2,%3};"
        : "+f"(c[0]), "+f"(c[1]), "+f"(c[2]), "+f"(c[3])
        : "r"(__float_as_uint(a[0])), "r"(__float_as_uint(a[1])),
          "r"(__float_as_uint(a[2])), "r"(__float_as_uint(a[3])),
          "r"(__float_as_uint(b[0])), "r"(__float_as_uint(b[1])));
}

__device__ __forceinline__ void cp_async16(void* dst_smem, const void* src) {
    unsigned d = (unsigned)__cvta_generic_to_shared(dst_smem);
    asm volatile("cp.async.cg.shared.global [%0], [%1], 16;\n" :: "r"(d), "l"(src));
}
#define CP_COMMIT() asm volatile("cp.async.commit_group;\n" ::: "memory")
#define CP_WAIT1()  asm volatile("cp.async.wait_group 1;\n" ::: "memory")

__device__ __forceinline__ float gelu_exact(float x) {
    return 0.5f * x * (1.0f + erff(x * 0.70710678118654752f));
}

// ---------------------------------------------------------------------------
// tf32 GEMM with 3-stage cp.async pipeline.
// BM=128 BN=128 BK=16, 256 threads (8 warps, 2x4), warp tile 64x32.
// fp32 staged raw into smem; tf32 truncation happens inside HMMA.
// ---------------------------------------------------------------------------
#define BM 128
#define BN 128
#define BK 16
#define ASTR 20
#define BSTR 136
#define STAGES 3
#define GEMM_SMEM_FLOATS (STAGES * (BM * ASTR + BK * BSTR))

#define COMPUTE_TILE(asb, bsb)                                                 \
    {                                                                          \
        _Pragma("unroll")                                                      \
        for (int ks = 0; ks < 2; ks++) {                                       \
            const int kk = ks * 8;                                             \
            float af[4][4], bf[4][2];                                          \
            _Pragma("unroll")                                                  \
            for (int mt = 0; mt < 4; mt++) {                                   \
                const int mr = wm * 64 + mt * 16;                              \
                af[mt][0] = (asb)[(mr + g) * ASTR + kk + tg];                  \
                af[mt][1] = (asb)[(mr + g + 8) * ASTR + kk + tg];              \
                af[mt][2] = (asb)[(mr + g) * ASTR + kk + tg + 4];              \
                af[mt][3] = (asb)[(mr + g + 8) * ASTR + kk + tg + 4];          \
            }                                                                  \
            _Pragma("unroll")                                                  \
            for (int nt = 0; nt < 4; nt++) {                                   \
                const int nc = wn * 32 + nt * 8 + g;                           \
                bf[nt][0] = (bsb)[(kk + tg) * BSTR + nc];                      \
                bf[nt][1] = (bsb)[(kk + tg + 4) * BSTR + nc];                  \
            }                                                                  \
            _Pragma("unroll")                                                  \
            for (int mt = 0; mt < 4; mt++)                                     \
                _Pragma("unroll")                                              \
                for (int nt = 0; nt < 4; nt++)                                 \
                    mma_tf32(acc[mt][nt], af[mt], bf[nt]);                     \
        }                                                                      \
    }

__global__ void __launch_bounds__(256)
tf32_gemm_kernel(const float* __restrict__ A,
                 const float* __restrict__ Bm,
                 const float* __restrict__ bias,
                 float* __restrict__ C,
                 int N, int K, int do_gelu)
{
    extern __shared__ float smem[];
    float* As = smem;                              // STAGES * BM*ASTR
    float* Bs = smem + STAGES * BM * ASTR;         // STAGES * BK*BSTR

    const int tid  = threadIdx.x;
    const int warp = tid >> 5, lane = tid & 31;
    const int wm = warp >> 2, wn = warp & 3;
    const int g = lane >> 2, tg = lane & 3;
    const int m0 = blockIdx.y * BM, n0 = blockIdx.x * BN;

    // async-copy mapping: 4 x 16B chunks per thread per tile
    const int a_row0 = tid >> 2;             // 0..63 (and +64)
    const int a_kc0  = (tid & 3) * 4;
    const int b_row0 = tid >> 5;             // 0..7 (and +8)
    const int b_nc0  = (tid & 31) * 4;

    const float* Ap  = A + (long long)m0 * K;
    const float* BpN = Bm + n0 + b_nc0;

    float acc[4][4][4];
#pragma unroll
    for (int i = 0; i < 4; i++)
#pragma unroll
        for (int j = 0; j < 4; j++)
#pragma unroll
            for (int r = 0; r < 4; r++) acc[i][j][r] = 0.0f;

#define ISSUE_TILE(s, k0)                                                      \
    {                                                                          \
        float* as = As + (s) * (BM * ASTR);                                    \
        float* bs = Bs + (s) * (BK * BSTR);                                    \
        cp_async16(&as[a_row0 * ASTR + a_kc0],                                 \
                   &Ap[(long long)a_row0 * K + (k0) + a_kc0]);                 \
        cp_async16(&as[(a_row0 + 64) * ASTR + a_kc0],                          \
                   &Ap[(long long)(a_row0 + 64) * K + (k0) + a_kc0]);          \
        cp_async16(&bs[b_row0 * BSTR + b_nc0],                                 \
                   &BpN[(long long)((k0) + b_row0) * N]);                      \
        cp_async16(&bs[(b_row0 + 8) * BSTR + b_nc0],                           \
                   &BpN[(long long)((k0) + b_row0 + 8) * N]);                  \
    }

    const int T = K / BK;
    ISSUE_TILE(0, 0); CP_COMMIT();
    ISSUE_TILE(1, BK); CP_COMMIT();
    CP_WAIT1();
    __syncthreads();

    int stage = 0;
    for (int i = 0; i < T; i++) {
        const int nt_ = i + 2;
        if (nt_ < T) {
            const int s2 = (stage + 2 >= STAGES) ? stage + 2 - STAGES : stage + 2;
            ISSUE_TILE(s2, nt_ * BK);
        }
        CP_COMMIT();
        const float* asb = As + stage * (BM * ASTR);
        const float* bsb = Bs + stage * (BK * BSTR);
        COMPUTE_TILE(asb, bsb);
        CP_WAIT1();
        __syncthreads();
        stage = (stage + 1 == STAGES) ? 0 : stage + 1;
    }
#undef ISSUE_TILE

    // epilogue
#pragma unroll
    for (int mt = 0; mt < 4; mt++) {
#pragma unroll
        for (int nt = 0; nt < 4; nt++) {
            const int row = m0 + wm * 64 + mt * 16 + g;
            const int col = n0 + wn * 32 + nt * 8 + 2 * tg;
            const float b0 = bias[col], b1 = bias[col + 1];
            float v0 = acc[mt][nt][0] + b0;
            float v1 = acc[mt][nt][1] + b1;
            float v2 = acc[mt][nt][2] + b0;
            float v3 = acc[mt][nt][3] + b1;
            if (do_gelu) {
                v0 = gelu_exact(v0); v1 = gelu_exact(v1);
                v2 = gelu_exact(v2); v3 = gelu_exact(v3);
            }
            *(float2*)&C[(long long)row * N + col] = make_float2(v0, v1);
            *(float2*)&C[(long long)(row + 8) * N + col] = make_float2(v2, v3);
        }
    }
}

// ---------------------------------------------------------------------------
// QKV GEMM with the same 3-stage cp.async pipeline; B columns map into
// Wqkv[h, k, e] (192-wide heads; 16B chunks never straddle a head boundary).
// Output scattered into Q/K/V [B,H,S,DH].
// ---------------------------------------------------------------------------
__global__ void __launch_bounds__(256)
tf32_qkv_kernel(const float* __restrict__ A,
                const float* __restrict__ Wqkv,
                float* __restrict__ Qo,
                float* __restrict__ Ko,
                float* __restrict__ Vo)
{
    extern __shared__ float smem[];
    float* As = smem;
    float* Bs = smem + STAGES * BM * ASTR;

    const int tid  = threadIdx.x;
    const int warp = tid >> 5, lane = tid & 31;
    const int wm = warp >> 2, wn = warp & 3;
    const int g = lane >> 2, tg = lane & 3;
    const int m0 = blockIdx.y * BM, n0 = blockIdx.x * BN;
    const int K = D_;

    const int a_row0 = tid >> 2;
    const int a_kc0  = (tid & 3) * 4;
    const int b_row0 = tid >> 5;
    const int b_nc0  = (tid & 31) * 4;

    // per-thread fixed B chunk column -> head/e mapping
    const int bcol  = n0 + b_nc0;
    const int bhead = bcol / 192;
    const int be    = bcol % 192;
    const float* BpH = Wqkv + (long long)bhead * D_ * 192 + be;

    const float* Ap = A + (long long)m0 * K;

    float acc[4][4][4];
#pragma unroll
    for (int i = 0; i < 4; i++)
#pragma unroll
        for (int j = 0; j < 4; j++)
#pragma unroll
            for (int r = 0; r < 4; r++) acc[i][j][r] = 0.0f;

#define ISSUE_TILE_Q(s, k0)                                                    \
    {                                                                          \
        float* as = As + (s) * (BM * ASTR);                                    \
        float* bs = Bs + (s) * (BK * BSTR);                                    \
        cp_async16(&as[a_row0 * ASTR + a_kc0],                                 \
                   &Ap[(long long)a_row0 * K + (k0) + a_kc0]);                 \
        cp_async16(&as[(a_row0 + 64) * ASTR + a_kc0],                          \
                   &Ap[(long long)(a_row0 + 64) * K + (k0) + a_kc0]);          \
        cp_async16(&bs[b_row0 * BSTR + b_nc0],                                 \
                   &BpH[(long long)((k0) + b_row0) * 192]);                    \
        cp_async16(&bs[(b_row0 + 8) * BSTR + b_nc0],                           \
                   &BpH[(long long)((k0) + b_row0 + 8) * 192]);                \
    }

    const int T = K / BK;
    ISSUE_TILE_Q(0, 0); CP_COMMIT();
    ISSUE_TILE_Q(1, BK); CP_COMMIT();
    CP_WAIT1();
    __syncthreads();

    int stage = 0;
    for (int i = 0; i < T; i++) {
        const int nt_ = i + 2;
        if (nt_ < T) {
            const int s2 = (stage + 2 >= STAGES) ? stage + 2 - STAGES : stage + 2;
            ISSUE_TILE_Q(s2, nt_ * BK);
        }
        CP_COMMIT();
        const float* asb = As + stage * (BM * ASTR);
        const float* bsb = Bs + stage * (BK * BSTR);
        COMPUTE_TILE(asb, bsb);
        CP_WAIT1();
        __syncthreads();
        stage = (stage + 1 == STAGES) ? 0 : stage + 1;
    }
#undef ISSUE_TILE_Q

    // epilogue: scatter to Q/K/V
#pragma unroll
    for (int mt = 0; mt < 4; mt++) {
#pragma unroll
        for (int nt = 0; nt < 4; nt++) {
            const int row = m0 + wm * 64 + mt * 16 + g;
            const int col = n0 + wn * 32 + nt * 8 + 2 * tg;
            const int head = col / 192;
            const int e = col % 192;
            float* dst = (e < 64) ? Qo : (e < 128) ? Ko : Vo;
            const int eo = e & 63;
            const int b = row >> 11, s = row & 2047;
            const long long base = (((long long)b * H_ + head) * S_ + s) * DH_ + eo;
            *(float2*)&dst[base] = make_float2(acc[mt][nt][0], acc[mt][nt][1]);
            *(float2*)&dst[base + 8LL * DH_] = make_float2(acc[mt][nt][2], acc[mt][nt][3]);
        }
    }
}

// ---------------------------------------------------------------------------
// Causal flash attention on tf32 tensor cores (unchanged from round 3).
// ---------------------------------------------------------------------------
__global__ void __launch_bounds__(256)
flash_attn_tc_kernel(const float* __restrict__ Q,
                     const float* __restrict__ K,
                     const float* __restrict__ V,
                     float* __restrict__ O)
{
    extern __shared__ float sm[];
    float* Qs = sm;                        // 128 x 68
    float* Ks = Qs + 128 * 68;             // 64 x 68
    float* Vs = Ks + 64 * 68;              // 64 x 72
    float* Ps = Vs + 64 * 72;              // 8 warps x 16 x 68

    const int tid = threadIdx.x;
    const int warp = tid >> 5, lane = tid & 31;
    const int g = lane >> 2, tg = lane & 3;
    const int i0 = blockIdx.x * 128;
    const int bh = blockIdx.y;

    const float* Qg = Q + (long long)bh * S_ * DH_;
    const float* Kg = K + (long long)bh * S_ * DH_;
    const float* Vg = V + (long long)bh * S_ * DH_;

#pragma unroll
    for (int i = 0; i < 8; i++) {
        int idx = tid + i * 256;
        int row = idx >> 4, col = (idx & 15) * 4;
        float4 v = *(const float4*)&Qg[(long long)(i0 + row) * DH_ + col];
        Qs[row * 68 + col + 0] = to_tf32(v.x * 0.125f);
        Qs[row * 68 + col + 1] = to_tf32(v.y * 0.125f);
        Qs[row * 68 + col + 2] = to_tf32(v.z * 0.125f);
        Qs[row * 68 + col + 3] = to_tf32(v.w * 0.125f);
    }

    float oacc[8][4];
#pragma unroll
    for (int nt = 0; nt < 8; nt++)
#pragma unroll
        for (int r = 0; r < 4; r++) oacc[nt][r] = 0.0f;

    float m0 = -1e30f, m1 = -1e30f, l0 = 0.0f, l1 = 0.0f;

    const int wrow0 = i0 + warp * 16;
    const int jtmax = (i0 + 127) >> 6;
    float* Pw = Ps + warp * 16 * 68;

    for (int jt = 0; jt <= jtmax; jt++) {
        const int j0 = jt << 6;
        __syncthreads();
#pragma unroll
        for (int i = 0; i < 4; i++) {
            int idx = tid + i * 256;
            int row = idx >> 4, col = (idx & 15) * 4;
            float4 kv = *(const float4*)&Kg[(long long)(j0 + row) * DH_ + col];
            Ks[row * 68 + col + 0] = to_tf32(kv.x);
            Ks[row * 68 + col + 1] = to_tf32(kv.y);
            Ks[row * 68 + col + 2] = to_tf32(kv.z);
            Ks[row * 68 + col + 3] = to_tf32(kv.w);
            float4 vv = *(const float4*)&Vg[(long long)(j0 + row) * DH_ + col];
            Vs[row * 72 + col + 0] = to_tf32(vv.x);
            Vs[row * 72 + col + 1] = to_tf32(vv.y);
            Vs[row * 72 + col + 2] = to_tf32(vv.z);
            Vs[row * 72 + col + 3] = to_tf32(vv.w);
        }
        __syncthreads();

        if (j0 > wrow0 + 15) continue;

        float sacc[8][4];
#pragma unroll
        for (int nt = 0; nt < 8; nt++)
#pragma unroll
            for (int r = 0; r < 4; r++) sacc[nt][r] = 0.0f;

#pragma unroll
        for (int kc = 0; kc < 8; kc++) {
            const int kk = kc * 8;
            float af[4];
            af[0] = Qs[(warp * 16 + g) * 68 + kk + tg];
            af[1] = Qs[(warp * 16 + g + 8) * 68 + kk + tg];
            af[2] = Qs[(warp * 16 + g) * 68 + kk + tg + 4];
            af[3] = Qs[(warp * 16 + g + 8) * 68 + kk + tg + 4];
#pragma unroll
            for (int nt = 0; nt < 8; nt++) {
                float bf[2];
                bf[0] = Ks[(nt * 8 + g) * 68 + kk + tg];
                bf[1] = Ks[(nt * 8 + g) * 68 + kk + tg + 4];
                mma_tf32(sacc[nt], af, bf);
            }
        }

        if (j0 + 63 > wrow0) {
            const int row0 = wrow0 + g, row1 = wrow0 + 8 + g;
#pragma unroll
            for (int nt = 0; nt < 8; nt++) {
                const int c0 = j0 + nt * 8 + 2 * tg;
                if (c0 > row0)     sacc[nt][0] = -1e30f;
                if (c0 + 1 > row0) sacc[nt][1] = -1e30f;
                if (c0 > row1)     sacc[nt][2] = -1e30f;
                if (c0 + 1 > row1) sacc[nt][3] = -1e30f;
            }
        }

        float rm0 = -1e30f, rm1 = -1e30f;
#pragma unroll
        for (int nt = 0; nt < 8; nt++) {
            rm0 = fmaxf(rm0, fmaxf(sacc[nt][0], sacc[nt][1]));
            rm1 = fmaxf(rm1, fmaxf(sacc[nt][2], sacc[nt][3]));
        }
        rm0 = fmaxf(rm0, __shfl_xor_sync(0xffffffffu, rm0, 1));
        rm0 = fmaxf(rm0, __shfl_xor_sync(0xffffffffu, rm0, 2));
        rm1 = fmaxf(rm1, __shfl_xor_sync(0xffffffffu, rm1, 1));
        rm1 = fmaxf(rm1, __shfl_xor_sync(0xffffffffu, rm1, 2));

        const float mn0 = fmaxf(m0, rm0), mn1 = fmaxf(m1, rm1);
        const float cr0 = __expf(m0 - mn0), cr1 = __expf(m1 - mn1);
        float rs0 = 0.0f, rs1 = 0.0f;
#pragma unroll
        for (int nt = 0; nt < 8; nt++) {
            float p0 = to_tf32(__expf(sacc[nt][0] - mn0));
            float p1 = to_tf32(__expf(sacc[nt][1] - mn0));
            float p2 = to_tf32(__expf(sacc[nt][2] - mn1));
            float p3 = to_tf32(__expf(sacc[nt][3] - mn1));
            rs0 += p0 + p1;
            rs1 += p2 + p3;
            sacc[nt][0] = p0; sacc[nt][1] = p1;
            sacc[nt][2] = p2; sacc[nt][3] = p3;
        }
        rs0 += __shfl_xor_sync(0xffffffffu, rs0, 1);
        rs0 += __shfl_xor_sync(0xffffffffu, rs0, 2);
        rs1 += __shfl_xor_sync(0xffffffffu, rs1, 1);
        rs1 += __shfl_xor_sync(0xffffffffu, rs1, 2);

        l0 = l0 * cr0 + rs0;
        l1 = l1 * cr1 + rs1;
        m0 = mn0; m1 = mn1;

#pragma unroll
        for (int nt = 0; nt < 8; nt++) {
            oacc[nt][0] *= cr0; oacc[nt][1] *= cr0;
            oacc[nt][2] *= cr1; oacc[nt][3] *= cr1;
        }

        __syncwarp();
#pragma unroll
        for (int nt = 0; nt < 8; nt++) {
            *(float2*)&Pw[g * 68 + nt * 8 + 2 * tg] =
                make_float2(sacc[nt][0], sacc[nt][1]);
            *(float2*)&Pw[(g + 8) * 68 + nt * 8 + 2 * tg] =
                make_float2(sacc[nt][2], sacc[nt][3]);
        }
        __syncwarp();

#pragma unroll
        for (int kc = 0; kc < 8; kc++) {
            const int kk = kc * 8;
            float af[4];
            af[0] = Pw[g * 68 + kk + tg];
            af[1] = Pw[(g + 8) * 68 + kk + tg];
            af[2] = Pw[g * 68 + kk + tg + 4];
            af[3] = Pw[(g + 8) * 68 + kk + tg + 4];
#pragma unroll
            for (int nt = 0; nt < 8; nt++) {
                float bf[2];
                bf[0] = Vs[(kk + tg) * 72 + nt * 8 + g];
                bf[1] = Vs[(kk + tg + 4) * 72 + nt * 8 + g];
                mma_tf32(oacc[nt], af, bf);
            }
        }
    }

    const int b = bh >> 4, h = bh & 15;
    const float inv0 = 1.0f / l0, inv1 = 1.0f / l1;
    const int row0 = wrow0 + g, row1 = wrow0 + 8 + g;
#pragma unroll
    for (int nt = 0; nt < 8; nt++) {
        const int col = h * 64 + nt * 8 + 2 * tg;
        *(float2*)&O[(long long)(b * S_ + row0) * D_ + col] =
            make_float2(oacc[nt][0] * inv0, oacc[nt][1] * inv0);
        *(float2*)&O[(long long)(b * S_ + row1) * D_ + col] =
            make_float2(oacc[nt][2] * inv1, oacc[nt][3] * inv1);
    }
}

// ---------------------------------------------------------------------------
// Fused residual + LayerNorm (unchanged)
// ---------------------------------------------------------------------------
__global__ void ln_kernel(const float* __restrict__ A,
                          const float* __restrict__ R,
                          const float* __restrict__ G,
                          const float* __restrict__ Be,
                          float* __restrict__ Out)
{
    const int row = blockIdx.x;
    const int tid = threadIdx.x;
    const long long base = (long long)row * D_;

    float4 va = *(const float4*)&A[base + tid * 4];
    float4 vb = *(const float4*)&R[base + tid * 4];
    float4 v = make_float4(va.x + vb.x, va.y + vb.y, va.z + vb.z, va.w + vb.w);

    float s = v.x + v.y + v.z + v.w;
    float ss = v.x * v.x + v.y * v.y + v.z * v.z + v.w * v.w;

    __shared__ float rs_[8], rss_[8];
#pragma unroll
    for (int off = 16; off >= 1; off >>= 1) {
        s += __shfl_xor_sync(0xffffffffu, s, off);
        ss += __shfl_xor_sync(0xffffffffu, ss, off);
    }
    int warp = tid >> 5, lane = tid & 31;
    if (lane == 0) { rs_[warp] = s; rss_[warp] = ss; }
    __syncthreads();
    if (warp == 0) {
        s = (lane < 8) ? rs_[lane] : 0.0f;
        ss = (lane < 8) ? rss_[lane] : 0.0f;
#pragma unroll
        for (int off = 4; off >= 1; off >>= 1) {
            s += __shfl_xor_sync(0xffffffffu, s, off);
            ss += __shfl_xor_sync(0xffffffffu, ss, off);
        }
        if (lane == 0) { rs_[0] = s; rss_[0] = ss; }
    }
    __syncthreads();
    s = rs_[0]; ss = rss_[0];

    const float mu = s * (1.0f / 1024.0f);
    const float var = ss * (1.0f / 1024.0f) - mu * mu;
    const float rstd = rsqrtf(var + 1e-5f);

    float4 g4 = *(const float4*)&G[tid * 4];
    float4 b4 = *(const float4*)&Be[tid * 4];
    float4 ov;
    ov.x = (v.x - mu) * rstd * g4.x + b4.x;
    ov.y = (v.y - mu) * rstd * g4.y + b4.y;
    ov.z = (v.z - mu) * rstd * g4.z + b4.z;
    ov.w = (v.w - mu) * rstd * g4.w + b4.w;
    *(float4*)&Out[base + tid * 4] = ov;
}

// ---------------------------------------------------------------------------
extern "C" void kernel_launch(void* const* d_in, const int* in_sizes, int n_in,
                              void* d_out, int out_size)
{
    (void)in_sizes; (void)n_in; (void)out_size;
    const float* x     = (const float*)d_in[0];
    const float* Wqkv  = (const float*)d_in[1];
    const float* Wproj = (const float*)d_in[2];
    const float* bproj = (const float*)d_in[3];
    const float* ln1g  = (const float*)d_in[4];
    const float* ln1b  = (const float*)d_in[5];
    const float* ln2g  = (const float*)d_in[6];
    const float* ln2b  = (const float*)d_in[7];
    const float* W1    = (const float*)d_in[8];
    const float* b1    = (const float*)d_in[9];
    const float* W2    = (const float*)d_in[10];
    const float* b2    = (const float*)d_in[11];
    float* out = (float*)d_out;

    float* scratch = nullptr;
    cudaGetSymbolAddress((void**)&scratch, g_scratch);

    float* Qb   = scratch + OFF_Q;
    float* Kb   = scratch + OFF_K;
    float* Vb   = scratch + OFF_V;
    float* ATT  = scratch + OFF_ATT;
    float* PROJ = scratch + OFF_PROJ;
    float* LN1  = scratch + OFF_LN1;
    float* FFH  = scratch + OFF_FFH;
    float* MLP  = scratch + OFF_MLP;

    const int gemm_smem = GEMM_SMEM_FLOATS * (int)sizeof(float);   // 56832 B
    cudaFuncSetAttribute(tf32_gemm_kernel,
                         cudaFuncAttributeMaxDynamicSharedMemorySize, gemm_smem);
    cudaFuncSetAttribute(tf32_qkv_kernel,
                         cudaFuncAttributeMaxDynamicSharedMemorySize, gemm_smem);

    // 1) QKV projection
    tf32_qkv_kernel<<<dim3(24, 64), 256, gemm_smem>>>(x, Wqkv, Qb, Kb, Vb);

    // 2) causal flash attention
    const int fa_smem = (128 * 68 + 64 * 68 + 64 * 72 + 8 * 16 * 68) * (int)sizeof(float);
    cudaFuncSetAttribute(flash_attn_tc_kernel,
                         cudaFuncAttributeMaxDynamicSharedMemorySize, fa_smem);
    flash_attn_tc_kernel<<<dim3(16, 64), 256, fa_smem>>>(Qb, Kb, Vb, ATT);

    // 3) output projection + bias
    tf32_gemm_kernel<<<dim3(8, 64), 256, gemm_smem>>>(ATT, Wproj, bproj, PROJ, 1024, 1024, 0);

    // 4) residual + LN1
    ln_kernel<<<8192, 256>>>(x, PROJ, ln1g, ln1b, LN1);

    // 5) MLP up + bias + exact GELU
    tf32_gemm_kernel<<<dim3(32, 64), 256, gemm_smem>>>(LN1, W1, b1, FFH, 4096, 1024, 1);

    // 6) MLP down + bias
    tf32_gemm_kernel<<<dim3(8, 64), 256, gemm_smem>>>(FFH, W2, b2, MLP, 1024, 4096, 0);

    // 7) residual + LN2 -> output
    ln_kernel<<<8192, 256>>>(LN1, MLP, ln2g, ln2b, out);
}